// round 2
// baseline (speedup 1.0000x reference)
#include <cuda_runtime.h>

// ---------------- constants ----------------
#define B_SZ   32
#define T_LEN  4096
#define CIN    64
#define HID    32
#define COUT   448
#define TILE   256
#define NT     256

typedef unsigned long long ull;

// f32x2 helpers (B300 packed fp32 FMA — only reachable via PTX)
__device__ __forceinline__ ull dup2(float x) {
    ull r; asm("mov.b64 %0, {%1, %1};" : "=l"(r) : "f"(x)); return r;
}
__device__ __forceinline__ void fma2(ull& a, ull b, ull c) {
    asm("fma.rn.f32x2 %0, %1, %2, %0;" : "+l"(a) : "l"(b), "l"(c));
}
__device__ __forceinline__ float2 up2(ull v) {
    float2 r; asm("mov.b64 {%0, %1}, %2;" : "=f"(r.x), "=f"(r.y) : "l"(v)); return r;
}

// tanh(g)*sigmoid(g) via a = e^{-g}:  (1-a^2) / ((1+a^2)*(1+a))
__device__ __forceinline__ float gact(float g) {
    float gc = fminf(fmaxf(g, -15.f), 15.f);
    float a  = __expf(-gc);
    float a2 = a * a;
    return __fdividef(1.f - a2, (1.f + a2) * (1.f + a));
}

// scratch: h = relu(w_sk1 * relu(skip) + b_sk1), [B*T, 32]
__device__ float g_h[B_SZ * T_LEN * HID];

// ---------------- smem layout (floats) for k_front ----------------
#define SXS     261                    // x row stride (64 rows of TILE+4, odd pad)
#define ZST     33                     // z row stride
#define OFF_SX    0                    // 64*261 = 16704
#define OFF_SZ0   16704                // 259*33 = 8547
#define OFF_SZ1   25252                // even; 258*33 = 8514
#define OFF_WC0   33766               // each K2 mat reorganized [ci][c], 2048
#define OFF_WC1   35814
#define OFF_WD00  37862               // 1024 each below
#define OFF_WD01  38886
#define OFF_WS0   39910
#define OFF_WO0   40934
#define OFF_WD10  41958
#define OFF_WD11  42982
#define OFF_WS1   44006
#define OFF_SK1   45030
#define OFF_BC    46054
#define OFF_BD0   46086
#define OFF_BS0   46118
#define OFF_BO0   46150
#define OFF_BD1   46182
#define OFF_BS1   46214
#define OFF_BK1   46246
#define OFF_SG0   46278               // 64: activated g0 for halo z1 rows
#define SMEM1_FLOATS 46342
#define SMEM1_BYTES  (SMEM1_FLOATS * 4)

__global__ __launch_bounds__(NT, 1)
void k_front(const float* __restrict__ x,
             const float* __restrict__ Wc,  const float* __restrict__ Bc,
             const float* __restrict__ Wd0, const float* __restrict__ Bd0,
             const float* __restrict__ Ws0, const float* __restrict__ Bs0,
             const float* __restrict__ Wo0, const float* __restrict__ Bo0,
             const float* __restrict__ Wd1, const float* __restrict__ Bd1,
             const float* __restrict__ Ws1, const float* __restrict__ Bs1,
             const float* __restrict__ Wk1, const float* __restrict__ Bk1)
{
    extern __shared__ float sm[];
    float* sx    = sm + OFF_SX;
    float* sz0   = sm + OFF_SZ0;
    float* sz1   = sm + OFF_SZ1;
    float* swc0  = sm + OFF_WC0;
    float* swc1  = sm + OFF_WC1;
    float* swd00 = sm + OFF_WD00;
    float* swd01 = sm + OFF_WD01;
    float* sws0  = sm + OFF_WS0;
    float* swo0  = sm + OFF_WO0;
    float* swd10 = sm + OFF_WD10;
    float* swd11 = sm + OFF_WD11;
    float* sws1  = sm + OFF_WS1;
    float* ssk1  = sm + OFF_SK1;
    float* sbc   = sm + OFF_BC;
    float* sbd0  = sm + OFF_BD0;
    float* sbs0  = sm + OFF_BS0;
    float* sbo0  = sm + OFF_BO0;
    float* sbd1  = sm + OFF_BD1;
    float* sbs1  = sm + OFF_BS1;
    float* sbk1  = sm + OFF_BK1;
    float* sg0   = sm + OFF_SG0;

    const int tid = threadIdx.x;
    const int b   = blockIdx.y;
    const int t0  = blockIdx.x * TILE;

    // ---- stage weights into smem, reorganized to [ci][c] for broadcast reads ----
    for (int idx = tid; idx < 2048; idx += NT) {
        int c = idx >> 6, ci = idx & 63;
        swc0[ci * 32 + c] = Wc[idx * 2 + 0];
        swc1[ci * 32 + c] = Wc[idx * 2 + 1];
    }
    for (int idx = tid; idx < 1024; idx += NT) {
        int c = idx >> 5, ci = idx & 31;
        swd00[ci * 32 + c] = Wd0[idx * 2 + 0];
        swd01[ci * 32 + c] = Wd0[idx * 2 + 1];
        swd10[ci * 32 + c] = Wd1[idx * 2 + 0];
        swd11[ci * 32 + c] = Wd1[idx * 2 + 1];
        sws0[ci * 32 + c]  = Ws0[idx];
        swo0[ci * 32 + c]  = Wo0[idx];
        sws1[ci * 32 + c]  = Ws1[idx];
        ssk1[ci * 32 + c]  = Wk1[idx];
    }
    if (tid < 32) {
        sbc[tid]  = Bc[tid];  sbd0[tid] = Bd0[tid];
        sbs0[tid] = Bs0[tid]; sbo0[tid] = Bo0[tid];
        sbd1[tid] = Bd1[tid]; sbs1[tid] = Bs1[tid];
        sbk1[tid] = Bk1[tid];
    }

    // ---- stage x tile (transposed: sx[ci][j], j = t-(t0-4)), halo 4 ----
    const float* xb = x + (size_t)b * T_LEN * CIN;
    for (int idx = tid; idx < (TILE + 4) * 16; idx += NT) {
        int j = idx >> 4, c4 = idx & 15;
        int t = t0 - 4 + j;
        float4 v = make_float4(0.f, 0.f, 0.f, 0.f);
        if (t >= 0) v = *(const float4*)(xb + (size_t)t * CIN + c4 * 4);
        sx[(c4 * 4 + 0) * SXS + j] = v.x;
        sx[(c4 * 4 + 1) * SXS + j] = v.y;
        sx[(c4 * 4 + 2) * SXS + j] = v.z;
        sx[(c4 * 4 + 3) * SXS + j] = v.w;
    }
    __syncthreads();

    // ---- stage z0: causal conv, rows i in [0,258] <-> t = t0-3+i ----
    for (int i = tid; i < TILE + 3; i += NT) {
        float* zr = sz0 + i * ZST;
        int t = t0 - 3 + i;
        if (t < 0) {
            #pragma unroll
            for (int c = 0; c < 32; c++) zr[c] = 0.f;
            continue;
        }
        ull acc[16];
        #pragma unroll
        for (int q = 0; q < 16; q++) acc[q] = *(const ull*)(sbc + 2 * q);
        #pragma unroll 8
        for (int ci = 0; ci < 64; ci++) {
            ull Xm = dup2(sx[ci * SXS + i]);        // x[t-1]
            ull Xc = dup2(sx[ci * SXS + i + 1]);    // x[t]
            const ull* W0 = (const ull*)(swc0 + ci * 32);
            const ull* W1 = (const ull*)(swc1 + ci * 32);
            #pragma unroll
            for (int q = 0; q < 16; q++) { fma2(acc[q], W0[q], Xm); fma2(acc[q], W1[q], Xc); }
        }
        #pragma unroll
        for (int q = 0; q < 16; q++) { float2 f = up2(acc[q]); zr[2*q] = f.x; zr[2*q+1] = f.y; }
    }
    __syncthreads();

    // ---- halo z1 rows r=0,1 (t = t0+r-2): step 1, activated g0, parallel over 64 lanes ----
    if (tid < 64) {
        int r = tid >> 5, c = tid & 31;
        int t = t0 + r - 2;
        float g = sbd0[c];
        if (t >= 0) {
            const float* zm = sz0 + r * ZST;        // z0[t-1]
            const float* zc = sz0 + (r + 1) * ZST;  // z0[t]
            #pragma unroll 8
            for (int ci = 0; ci < 32; ci++)
                g += swd00[ci * 32 + c] * zm[ci] + swd01[ci * 32 + c] * zc[ci];
            sg0[tid] = gact(g);
        } else sg0[tid] = 0.f;
    }

    // ---- block 0 main: thread owns tile-local t = tid (always >= 0) ----
    ull sk[16];   // skip accumulator, lives until the end
    {
        const int tl = tid;
        const float* zm = sz0 + (tl + 2) * ZST;     // z0[t-1]
        const float* zc = sz0 + (tl + 3) * ZST;     // z0[t]
        ull acc[16];
        #pragma unroll
        for (int q = 0; q < 16; q++) acc[q] = *(const ull*)(sbd0 + 2 * q);
        #pragma unroll 8
        for (int ci = 0; ci < 32; ci++) {
            ull Zm = dup2(zm[ci]), Zc = dup2(zc[ci]);
            const ull* W0 = (const ull*)(swd00 + ci * 32);
            const ull* W1 = (const ull*)(swd01 + ci * 32);
            #pragma unroll
            for (int q = 0; q < 16; q++) { fma2(acc[q], W0[q], Zm); fma2(acc[q], W1[q], Zc); }
        }
        float a0f[32];
        #pragma unroll
        for (int q = 0; q < 16; q++) {
            float2 f = up2(acc[q]);
            a0f[2*q] = gact(f.x); a0f[2*q+1] = gact(f.y);
        }
        ull zo[16];
        #pragma unroll
        for (int q = 0; q < 16; q++) {
            sk[q] = *(const ull*)(sbs0 + 2 * q);
            zo[q] = *(const ull*)(sbo0 + 2 * q);
        }
        #pragma unroll
        for (int ci = 0; ci < 32; ci++) {
            ull A = dup2(a0f[ci]);
            const ull* Ws = (const ull*)(sws0 + ci * 32);
            const ull* Wo = (const ull*)(swo0 + ci * 32);
            #pragma unroll
            for (int q = 0; q < 16; q++) { fma2(sk[q], Ws[q], A); fma2(zo[q], Wo[q], A); }
        }
        float* z1r = sz1 + (tl + 2) * ZST;          // z1[t] = wo0*a0 + bo0 + z0[t]
        #pragma unroll
        for (int q = 0; q < 16; q++) {
            float2 f = up2(zo[q]);
            z1r[2*q]   = f.x + zc[2*q];
            z1r[2*q+1] = f.y + zc[2*q+1];
        }
    }
    __syncthreads();

    // ---- halo z1 rows: step 2 ----
    if (tid < 64) {
        int r = tid >> 5, c = tid & 31;
        int t = t0 + r - 2;
        float v = 0.f;
        if (t >= 0) {
            v = sbo0[c] + sz0[(r + 1) * ZST + c];
            #pragma unroll 8
            for (int ci = 0; ci < 32; ci++) v += swo0[ci * 32 + c] * sg0[r * 32 + ci];
        }
        sz1[r * ZST + c] = v;
    }
    __syncthreads();

    // ---- block 1 (dil 2) + skip head; thread owns tile-local t = tid ----
    {
        const int tl = tid;
        const float* zm = sz1 + tl * ZST;           // z1[t-2]
        const float* zc = sz1 + (tl + 2) * ZST;     // z1[t]
        ull acc[16];
        #pragma unroll
        for (int q = 0; q < 16; q++) acc[q] = *(const ull*)(sbd1 + 2 * q);
        #pragma unroll 8
        for (int ci = 0; ci < 32; ci++) {
            ull Zm = dup2(zm[ci]), Zc = dup2(zc[ci]);
            const ull* W0 = (const ull*)(swd10 + ci * 32);
            const ull* W1 = (const ull*)(swd11 + ci * 32);
            #pragma unroll
            for (int q = 0; q < 16; q++) { fma2(acc[q], W0[q], Zm); fma2(acc[q], W1[q], Zc); }
        }
        float a1f[32];
        #pragma unroll
        for (int q = 0; q < 16; q++) {
            float2 f = up2(acc[q]);
            a1f[2*q] = gact(f.x); a1f[2*q+1] = gact(f.y);
        }
        #pragma unroll
        for (int ci = 0; ci < 32; ci++) {
            ull A = dup2(a1f[ci]);
            const ull* Ws = (const ull*)(sws1 + ci * 32);
            #pragma unroll
            for (int q = 0; q < 16; q++) fma2(sk[q], Ws[q], A);
        }
        // s = relu(skip + bs1); v = relu(w_sk1*s + b_sk1)
        float s[32];
        #pragma unroll
        for (int q = 0; q < 16; q++) {
            float2 f = up2(sk[q]);
            s[2*q]   = fmaxf(f.x + sbs1[2*q],   0.f);
            s[2*q+1] = fmaxf(f.y + sbs1[2*q+1], 0.f);
        }
        ull vv[16];
        #pragma unroll
        for (int q = 0; q < 16; q++) vv[q] = *(const ull*)(sbk1 + 2 * q);
        #pragma unroll
        for (int ci = 0; ci < 32; ci++) {
            ull A = dup2(s[ci]);
            const ull* Ws = (const ull*)(ssk1 + ci * 32);
            #pragma unroll
            for (int q = 0; q < 16; q++) fma2(vv[q], Ws[q], A);
        }
        float* hp = g_h + ((size_t)(b * T_LEN + t0 + tl)) * HID;
        #pragma unroll
        for (int q = 0; q < 16; q += 2) {
            float2 fa = up2(vv[q]), fb = up2(vv[q + 1]);
            float4 o = make_float4(fmaxf(fa.x, 0.f), fmaxf(fa.y, 0.f),
                                   fmaxf(fb.x, 0.f), fmaxf(fb.y, 0.f));
            ((float4*)hp)[q >> 1] = o;
        }
    }
}

// ---------------- kernel 2: out[M,448] = h[M,32] @ w_sk2^T + b ----------------
// block tile: 256 rows x 64 cols; thread tile 8t x 8j; f32x2 paired along t.
#define SHS 258
__global__ __launch_bounds__(256, 2)
void k_out(const float* __restrict__ W2, const float* __restrict__ B2,
           float* __restrict__ out)
{
    __shared__ __align__(16) float sh[32 * SHS];   // h transposed: [k][t]
    __shared__ __align__(16) float sw[32 * 64];    // w: [k][j]
    __shared__ float sb[64];

    const int tid = threadIdx.x;
    const int jB  = blockIdx.x * 64;
    const int mB  = blockIdx.y * 256;

    const float4* gh4 = (const float4*)g_h + (size_t)mB * 8;
    for (int idx = tid; idx < 256 * 8; idx += 256) {
        int tl = idx >> 3, k4 = idx & 7;
        float4 v = gh4[(size_t)tl * 8 + k4];
        sh[(k4 * 4 + 0) * SHS + tl] = v.x;
        sh[(k4 * 4 + 1) * SHS + tl] = v.y;
        sh[(k4 * 4 + 2) * SHS + tl] = v.z;
        sh[(k4 * 4 + 3) * SHS + tl] = v.w;
    }
    for (int idx = tid; idx < 64 * 32; idx += 256) {
        int jl = idx >> 5, k = idx & 31;
        sw[k * 64 + jl] = W2[(size_t)(jB + jl) * 32 + k];
    }
    if (tid < 64) sb[tid] = B2[jB + tid];
    __syncthreads();

    const int tx = tid & 7, ty = tid >> 3;
    const int j0 = tx * 8, tt0 = ty * 8;

    ull acc[4][8];
    #pragma unroll
    for (int bq = 0; bq < 8; bq++) {
        ull bias = dup2(sb[j0 + bq]);
        #pragma unroll
        for (int a = 0; a < 4; a++) acc[a][bq] = bias;
    }

    #pragma unroll 8
    for (int k = 0; k < 32; k++) {
        const ull* hp = (const ull*)(sh + k * SHS + tt0);
        ull H0 = hp[0], H1 = hp[1], H2 = hp[2], H3 = hp[3];
        const float4* wp = (const float4*)(sw + k * 64 + j0);
        float4 wa = wp[0], wb = wp[1];
        ull W[8] = { dup2(wa.x), dup2(wa.y), dup2(wa.z), dup2(wa.w),
                     dup2(wb.x), dup2(wb.y), dup2(wb.z), dup2(wb.w) };
        #pragma unroll
        for (int bq = 0; bq < 8; bq++) {
            fma2(acc[0][bq], H0, W[bq]);
            fma2(acc[1][bq], H1, W[bq]);
            fma2(acc[2][bq], H2, W[bq]);
            fma2(acc[3][bq], H3, W[bq]);
        }
    }

    #pragma unroll
    for (int a = 0; a < 4; a++) {
        float lo[8], hi[8];
        #pragma unroll
        for (int bq = 0; bq < 8; bq++) {
            float2 f = up2(acc[a][bq]);
            lo[bq] = f.x; hi[bq] = f.y;
        }
        size_t m0 = (size_t)(mB + tt0 + 2 * a) * COUT + jB + j0;
        ((float4*)(out + m0))[0]        = make_float4(lo[0], lo[1], lo[2], lo[3]);
        ((float4*)(out + m0))[1]        = make_float4(lo[4], lo[5], lo[6], lo[7]);
        ((float4*)(out + m0 + COUT))[0] = make_float4(hi[0], hi[1], hi[2], hi[3]);
        ((float4*)(out + m0 + COUT))[1] = make_float4(hi[4], hi[5], hi[6], hi[7]);
    }
}

// ---------------- launch ----------------
extern "C" void kernel_launch(void* const* d_in, const int* in_sizes, int n_in,
                              void* d_out, int out_size)
{
    (void)in_sizes; (void)n_in; (void)out_size;
    const float* x   = (const float*)d_in[0];
    const float* Wc  = (const float*)d_in[1];
    const float* Bc  = (const float*)d_in[2];
    const float* Wd0 = (const float*)d_in[3];
    const float* Bd0 = (const float*)d_in[4];
    const float* Ws0 = (const float*)d_in[5];
    const float* Bs0 = (const float*)d_in[6];
    const float* Wo0 = (const float*)d_in[7];
    const float* Bo0 = (const float*)d_in[8];
    const float* Wd1 = (const float*)d_in[9];
    const float* Bd1 = (const float*)d_in[10];
    const float* Ws1 = (const float*)d_in[11];
    const float* Bs1 = (const float*)d_in[12];
    // d_in[13]=wo1, d_in[14]=bo1: dead branch (z after block 1 is never used)
    const float* Wk1 = (const float*)d_in[15];
    const float* Bk1 = (const float*)d_in[16];
    const float* W2  = (const float*)d_in[17];
    const float* B2  = (const float*)d_in[18];
    float* out = (float*)d_out;

    cudaFuncSetAttribute(k_front, cudaFuncAttributeMaxDynamicSharedMemorySize, SMEM1_BYTES);

    dim3 g1(T_LEN / TILE, B_SZ);     // 16 x 32 = 512 blocks
    k_front<<<g1, NT, SMEM1_BYTES>>>(x, Wc, Bc, Wd0, Bd0, Ws0, Bs0, Wo0, Bo0,
                                     Wd1, Bd1, Ws1, Bs1, Wk1, Bk1);

    dim3 g2(COUT / 64, (B_SZ * T_LEN) / 256);  // 7 x 512 = 3584 blocks
    k_out<<<g2, 256>>>(W2, B2, out);
}

// round 4
// speedup vs baseline: 1.0634x; 1.0634x over previous
#include <cuda_runtime.h>
#include <cstdint>

// ---------------- constants ----------------
#define B_SZ   32
#define T_LEN  4096
#define CIN    64
#define HID    32
#define COUT   448
#define TILE   256
#define NT     256

typedef unsigned long long ull;

// f32x2 helpers (B300 packed fp32 FMA — only reachable via PTX)
__device__ __forceinline__ ull dup2(float x) {
    ull r; asm("mov.b64 %0, {%1, %1};" : "=l"(r) : "f"(x)); return r;
}
__device__ __forceinline__ void fma2(ull& a, ull b, ull c) {
    asm("fma.rn.f32x2 %0, %1, %2, %0;" : "+l"(a) : "l"(b), "l"(c));
}
__device__ __forceinline__ float2 up2(ull v) {
    float2 r; asm("mov.b64 {%0, %1}, %2;" : "=f"(r.x), "=f"(r.y) : "l"(v)); return r;
}

// tanh(g)*sigmoid(g) via a = e^{-g}:  (1-a^2) / ((1+a^2)*(1+a))
__device__ __forceinline__ float gact(float g) {
    float gc = fminf(fmaxf(g, -15.f), 15.f);
    float a  = __expf(-gc);
    float a2 = a * a;
    return __fdividef(1.f - a2, (1.f + a2) * (1.f + a));
}

// scratch: h = relu(w_sk1 * relu(skip) + b_sk1), [B*T, 32]
__device__ float g_h[B_SZ * T_LEN * HID];

// ---------------- smem layout (floats) for k_front ----------------
#define SXS     261                    // x row stride (64 rows of TILE+4, odd pad)
#define ZST     33                     // z row stride
#define OFF_SX    0                    // 64*261 = 16704
#define OFF_SZ0   16704                // 259*33 = 8547
#define OFF_SZ1   25252                // even; 258*33 = 8514
#define OFF_WC0   33766               // each K2 mat reorganized [ci][c], 2048
#define OFF_WC1   35814
#define OFF_WD00  37862               // 1024 each below
#define OFF_WD01  38886
#define OFF_WS0   39910
#define OFF_WO0   40934
#define OFF_WD10  41958
#define OFF_WD11  42982
#define OFF_WS1   44006
#define OFF_SK1   45030
#define OFF_BC    46054
#define OFF_BD0   46086
#define OFF_BS0   46118
#define OFF_BO0   46150
#define OFF_BD1   46182
#define OFF_BS1   46214
#define OFF_BK1   46246
#define OFF_SG0   46278               // 64: activated g0 for halo z1 rows
#define SMEM1_FLOATS 46342
#define SMEM1_BYTES  (SMEM1_FLOATS * 4)

__global__ __launch_bounds__(NT, 1)
void k_front(const float* __restrict__ x,
             const float* __restrict__ Wc,  const float* __restrict__ Bc,
             const float* __restrict__ Wd0, const float* __restrict__ Bd0,
             const float* __restrict__ Ws0, const float* __restrict__ Bs0,
             const float* __restrict__ Wo0, const float* __restrict__ Bo0,
             const float* __restrict__ Wd1, const float* __restrict__ Bd1,
             const float* __restrict__ Ws1, const float* __restrict__ Bs1,
             const float* __restrict__ Wk1, const float* __restrict__ Bk1)
{
    extern __shared__ float sm[];
    float* sx    = sm + OFF_SX;
    float* sz0   = sm + OFF_SZ0;
    float* sz1   = sm + OFF_SZ1;
    float* swc0  = sm + OFF_WC0;
    float* swc1  = sm + OFF_WC1;
    float* swd00 = sm + OFF_WD00;
    float* swd01 = sm + OFF_WD01;
    float* sws0  = sm + OFF_WS0;
    float* swo0  = sm + OFF_WO0;
    float* swd10 = sm + OFF_WD10;
    float* swd11 = sm + OFF_WD11;
    float* sws1  = sm + OFF_WS1;
    float* ssk1  = sm + OFF_SK1;
    float* sbc   = sm + OFF_BC;
    float* sbd0  = sm + OFF_BD0;
    float* sbs0  = sm + OFF_BS0;
    float* sbo0  = sm + OFF_BO0;
    float* sbd1  = sm + OFF_BD1;
    float* sbs1  = sm + OFF_BS1;
    float* sbk1  = sm + OFF_BK1;
    float* sg0   = sm + OFF_SG0;

    const int tid = threadIdx.x;
    const int b   = blockIdx.y;
    const int t0  = blockIdx.x * TILE;

    // ---- stage weights into smem, reorganized to [ci][c] for broadcast reads ----
    for (int idx = tid; idx < 2048; idx += NT) {
        int c = idx >> 6, ci = idx & 63;
        swc0[ci * 32 + c] = Wc[idx * 2 + 0];
        swc1[ci * 32 + c] = Wc[idx * 2 + 1];
    }
    for (int idx = tid; idx < 1024; idx += NT) {
        int c = idx >> 5, ci = idx & 31;
        swd00[ci * 32 + c] = Wd0[idx * 2 + 0];
        swd01[ci * 32 + c] = Wd0[idx * 2 + 1];
        swd10[ci * 32 + c] = Wd1[idx * 2 + 0];
        swd11[ci * 32 + c] = Wd1[idx * 2 + 1];
        sws0[ci * 32 + c]  = Ws0[idx];
        swo0[ci * 32 + c]  = Wo0[idx];
        sws1[ci * 32 + c]  = Ws1[idx];
        ssk1[ci * 32 + c]  = Wk1[idx];
    }
    if (tid < 32) {
        sbc[tid]  = Bc[tid];  sbd0[tid] = Bd0[tid];
        sbs0[tid] = Bs0[tid]; sbo0[tid] = Bo0[tid];
        sbd1[tid] = Bd1[tid]; sbs1[tid] = Bs1[tid];
        sbk1[tid] = Bk1[tid];
    }

    // ---- stage x tile (transposed: sx[ci][j], j = t-(t0-4)), halo 4 ----
    const float* xb = x + (size_t)b * T_LEN * CIN;
    for (int idx = tid; idx < (TILE + 4) * 16; idx += NT) {
        int j = idx >> 4, c4 = idx & 15;
        int t = t0 - 4 + j;
        float4 v = make_float4(0.f, 0.f, 0.f, 0.f);
        if (t >= 0) v = *(const float4*)(xb + (size_t)t * CIN + c4 * 4);
        sx[(c4 * 4 + 0) * SXS + j] = v.x;
        sx[(c4 * 4 + 1) * SXS + j] = v.y;
        sx[(c4 * 4 + 2) * SXS + j] = v.z;
        sx[(c4 * 4 + 3) * SXS + j] = v.w;
    }
    __syncthreads();

    // ---- stage z0: causal conv, rows i in [0,258] <-> t = t0-3+i ----
    for (int i = tid; i < TILE + 3; i += NT) {
        float* zr = sz0 + i * ZST;
        int t = t0 - 3 + i;
        if (t < 0) {
            #pragma unroll
            for (int c = 0; c < 32; c++) zr[c] = 0.f;
            continue;
        }
        ull acc[16];
        #pragma unroll
        for (int q = 0; q < 16; q++) acc[q] = *(const ull*)(sbc + 2 * q);
        #pragma unroll 8
        for (int ci = 0; ci < 64; ci++) {
            ull Xm = dup2(sx[ci * SXS + i]);        // x[t-1]
            ull Xc = dup2(sx[ci * SXS + i + 1]);    // x[t]
            const ull* W0 = (const ull*)(swc0 + ci * 32);
            const ull* W1 = (const ull*)(swc1 + ci * 32);
            #pragma unroll
            for (int q = 0; q < 16; q++) { fma2(acc[q], W0[q], Xm); fma2(acc[q], W1[q], Xc); }
        }
        #pragma unroll
        for (int q = 0; q < 16; q++) { float2 f = up2(acc[q]); zr[2*q] = f.x; zr[2*q+1] = f.y; }
    }
    __syncthreads();

    // ---- halo z1 rows r=0,1 (t = t0+r-2): step 1, activated g0, parallel over 64 lanes ----
    if (tid < 64) {
        int r = tid >> 5, c = tid & 31;
        int t = t0 + r - 2;
        float g = sbd0[c];
        if (t >= 0) {
            const float* zm = sz0 + r * ZST;        // z0[t-1]
            const float* zc = sz0 + (r + 1) * ZST;  // z0[t]
            #pragma unroll 8
            for (int ci = 0; ci < 32; ci++)
                g += swd00[ci * 32 + c] * zm[ci] + swd01[ci * 32 + c] * zc[ci];
            sg0[tid] = gact(g);
        } else sg0[tid] = 0.f;
    }

    // ---- block 0 main: thread owns tile-local t = tid (always >= 0) ----
    ull sk[16];   // skip accumulator, lives until the end
    {
        const int tl = tid;
        const float* zm = sz0 + (tl + 2) * ZST;     // z0[t-1]
        const float* zc = sz0 + (tl + 3) * ZST;     // z0[t]
        ull acc[16];
        #pragma unroll
        for (int q = 0; q < 16; q++) acc[q] = *(const ull*)(sbd0 + 2 * q);
        #pragma unroll 8
        for (int ci = 0; ci < 32; ci++) {
            ull Zm = dup2(zm[ci]), Zc = dup2(zc[ci]);
            const ull* W0 = (const ull*)(swd00 + ci * 32);
            const ull* W1 = (const ull*)(swd01 + ci * 32);
            #pragma unroll
            for (int q = 0; q < 16; q++) { fma2(acc[q], W0[q], Zm); fma2(acc[q], W1[q], Zc); }
        }
        float a0f[32];
        #pragma unroll
        for (int q = 0; q < 16; q++) {
            float2 f = up2(acc[q]);
            a0f[2*q] = gact(f.x); a0f[2*q+1] = gact(f.y);
        }
        ull zo[16];
        #pragma unroll
        for (int q = 0; q < 16; q++) {
            sk[q] = *(const ull*)(sbs0 + 2 * q);
            zo[q] = *(const ull*)(sbo0 + 2 * q);
        }
        #pragma unroll
        for (int ci = 0; ci < 32; ci++) {
            ull A = dup2(a0f[ci]);
            const ull* Ws = (const ull*)(sws0 + ci * 32);
            const ull* Wo = (const ull*)(swo0 + ci * 32);
            #pragma unroll
            for (int q = 0; q < 16; q++) { fma2(sk[q], Ws[q], A); fma2(zo[q], Wo[q], A); }
        }
        float* z1r = sz1 + (tl + 2) * ZST;          // z1[t] = wo0*a0 + bo0 + z0[t]
        #pragma unroll
        for (int q = 0; q < 16; q++) {
            float2 f = up2(zo[q]);
            z1r[2*q]   = f.x + zc[2*q];
            z1r[2*q+1] = f.y + zc[2*q+1];
        }
    }
    __syncthreads();

    // ---- halo z1 rows: step 2 ----
    if (tid < 64) {
        int r = tid >> 5, c = tid & 31;
        int t = t0 + r - 2;
        float v = 0.f;
        if (t >= 0) {
            v = sbo0[c] + sz0[(r + 1) * ZST + c];
            #pragma unroll 8
            for (int ci = 0; ci < 32; ci++) v += swo0[ci * 32 + c] * sg0[r * 32 + ci];
        }
        sz1[r * ZST + c] = v;
    }
    __syncthreads();

    // ---- block 1 (dil 2) + skip head; thread owns tile-local t = tid ----
    {
        const int tl = tid;
        const float* zm = sz1 + tl * ZST;           // z1[t-2]
        const float* zc = sz1 + (tl + 2) * ZST;     // z1[t]
        ull acc[16];
        #pragma unroll
        for (int q = 0; q < 16; q++) acc[q] = *(const ull*)(sbd1 + 2 * q);
        #pragma unroll 8
        for (int ci = 0; ci < 32; ci++) {
            ull Zm = dup2(zm[ci]), Zc = dup2(zc[ci]);
            const ull* W0 = (const ull*)(swd10 + ci * 32);
            const ull* W1 = (const ull*)(swd11 + ci * 32);
            #pragma unroll
            for (int q = 0; q < 16; q++) { fma2(acc[q], W0[q], Zm); fma2(acc[q], W1[q], Zc); }
        }
        float a1f[32];
        #pragma unroll
        for (int q = 0; q < 16; q++) {
            float2 f = up2(acc[q]);
            a1f[2*q] = gact(f.x); a1f[2*q+1] = gact(f.y);
        }
        #pragma unroll
        for (int ci = 0; ci < 32; ci++) {
            ull A = dup2(a1f[ci]);
            const ull* Ws = (const ull*)(sws1 + ci * 32);
            #pragma unroll
            for (int q = 0; q < 16; q++) fma2(sk[q], Ws[q], A);
        }
        // s = relu(skip + bs1); v = relu(w_sk1*s + b_sk1)
        float s[32];
        #pragma unroll
        for (int q = 0; q < 16; q++) {
            float2 f = up2(sk[q]);
            s[2*q]   = fmaxf(f.x + sbs1[2*q],   0.f);
            s[2*q+1] = fmaxf(f.y + sbs1[2*q+1], 0.f);
        }
        ull vv[16];
        #pragma unroll
        for (int q = 0; q < 16; q++) vv[q] = *(const ull*)(sbk1 + 2 * q);
        #pragma unroll
        for (int ci = 0; ci < 32; ci++) {
            ull A = dup2(s[ci]);
            const ull* Ws = (const ull*)(ssk1 + ci * 32);
            #pragma unroll
            for (int q = 0; q < 16; q++) fma2(vv[q], Ws[q], A);
        }
        float* hp = g_h + ((size_t)(b * T_LEN + t0 + tl)) * HID;
        #pragma unroll
        for (int q = 0; q < 16; q += 2) {
            float2 fa = up2(vv[q]), fb = up2(vv[q + 1]);
            float4 o = make_float4(fmaxf(fa.x, 0.f), fmaxf(fa.y, 0.f),
                                   fmaxf(fb.x, 0.f), fmaxf(fb.y, 0.f));
            ((float4*)hp)[q >> 1] = o;
        }
    }
}

// ============ kernel 2 (tensor cores): out[M,448] = h[M,32] @ W2^T + b ============
// tf32 mma.sync m16n8k8 with full 3-term split (fp32-accurate):
//   out = Hh*Wh + Hh*Wl + Hl*Wh   (Hl*Wl term ~2^-22, dropped)
// CTA tile 256x64, 8 warps as 4(M) x 2(N); warp tile 64x32.
// smem strides 36 -> fragment LDS bank = 4*(lane/4)+lane%4 : conflict-free.

#define KO_SH_HI 0        // 256*36 = 9216
#define KO_SH_LO 9216     // 9216
#define KO_SW_HI 18432    // 64*36 = 2304
#define KO_SW_LO 20736    // 2304
#define KO_SB    23040    // 64
#define KO_SMEM_FLOATS 23104
#define KO_SMEM_BYTES (KO_SMEM_FLOATS * 4)

__device__ __forceinline__ uint32_t tf32_rna(float x) {
    uint32_t r; asm("cvt.rna.tf32.f32 %0, %1;" : "=r"(r) : "f"(x)); return r;
}
__device__ __forceinline__ void mma_tf32(float* d, const uint32_t* a,
                                         uint32_t b0, uint32_t b1) {
    asm("mma.sync.aligned.m16n8k8.row.col.f32.tf32.tf32.f32 "
        "{%0,%1,%2,%3}, {%4,%5,%6,%7}, {%8,%9}, {%0,%1,%2,%3};"
        : "+f"(d[0]), "+f"(d[1]), "+f"(d[2]), "+f"(d[3])
        : "r"(a[0]), "r"(a[1]), "r"(a[2]), "r"(a[3]), "r"(b0), "r"(b1));
}

__global__ __launch_bounds__(256, 2)
void k_out_tc(const float* __restrict__ W2, const float* __restrict__ B2,
              float* __restrict__ out)
{
    extern __shared__ float sm[];
    const int tid  = threadIdx.x;
    const int lane = tid & 31;
    const int wid  = tid >> 5;
    const int warpM = wid & 3;      // 4 warps along M (64 rows each)
    const int warpN = wid >> 2;     // 2 warps along N (32 cols each)
    const int jB = blockIdx.x * 64;
    const int mB = blockIdx.y * 256;

    // ---- stage h tile [256][32] -> hi/lo tf32, row stride 36 ----
    const float4* gh4 = (const float4*)g_h + (size_t)mB * 8;
    for (int idx = tid; idx < 2048; idx += 256) {
        int tl = idx >> 3, c4 = idx & 7;
        float4 v = gh4[(size_t)tl * 8 + c4];
        float e[4] = {v.x, v.y, v.z, v.w};
        int base = tl * 36 + c4 * 4;
        #pragma unroll
        for (int q = 0; q < 4; q++) {
            uint32_t hb = tf32_rna(e[q]);
            float hf = __uint_as_float(hb);
            uint32_t lb = tf32_rna(e[q] - hf);
            sm[KO_SH_HI + base + q] = hf;
            sm[KO_SH_LO + base + q] = __uint_as_float(lb);
        }
    }
    // ---- stage W2 slice [64 n][32 k] -> hi/lo, row stride 36 (n-major) ----
    for (int idx = tid; idx < 2048; idx += 256) {
        int jl = idx >> 5, k = idx & 31;
        float w = W2[(size_t)(jB + jl) * 32 + k];
        uint32_t hb = tf32_rna(w);
        float hf = __uint_as_float(hb);
        uint32_t lb = tf32_rna(w - hf);
        sm[KO_SW_HI + jl * 36 + k] = hf;
        sm[KO_SW_LO + jl * 36 + k] = __uint_as_float(lb);
    }
    if (tid < 64) sm[KO_SB + tid] = B2[jB + tid];
    __syncthreads();

    float d[4][4][4];
    #pragma unroll
    for (int m = 0; m < 4; m++)
        #pragma unroll
        for (int n = 0; n < 4; n++)
            #pragma unroll
            for (int c = 0; c < 4; c++) d[m][n][c] = 0.f;

    const int rbase = warpM * 64 + (lane >> 2);
    const int cA    = lane & 3;
    const int nbase = warpN * 32 + (lane >> 2);

    #pragma unroll
    for (int kk = 0; kk < 4; kk++) {
        uint32_t ah[4][4], al[4][4];
        #pragma unroll
        for (int m = 0; m < 4; m++) {
            int r0 = rbase + m * 16;
            int c0 = kk * 8 + cA;
            ah[m][0] = __float_as_uint(sm[KO_SH_HI + (r0    ) * 36 + c0    ]);
            ah[m][1] = __float_as_uint(sm[KO_SH_HI + (r0 + 8) * 36 + c0    ]);
            ah[m][2] = __float_as_uint(sm[KO_SH_HI + (r0    ) * 36 + c0 + 4]);
            ah[m][3] = __float_as_uint(sm[KO_SH_HI + (r0 + 8) * 36 + c0 + 4]);
            al[m][0] = __float_as_uint(sm[KO_SH_LO + (r0    ) * 36 + c0    ]);
            al[m][1] = __float_as_uint(sm[KO_SH_LO + (r0 + 8) * 36 + c0    ]);
            al[m][2] = __float_as_uint(sm[KO_SH_LO + (r0    ) * 36 + c0 + 4]);
            al[m][3] = __float_as_uint(sm[KO_SH_LO + (r0 + 8) * 36 + c0 + 4]);
        }
        #pragma unroll
        for (int n = 0; n < 4; n++) {
            int cn = (nbase + n * 8) * 36 + kk * 8 + cA;
            uint32_t bh0 = __float_as_uint(sm[KO_SW_HI + cn    ]);
            uint32_t bh1 = __float_as_uint(sm[KO_SW_HI + cn + 4]);
            uint32_t bl0 = __float_as_uint(sm[KO_SW_LO + cn    ]);
            uint32_t bl1 = __float_as_uint(sm[KO_SW_LO + cn + 4]);
            #pragma unroll
            for (int m = 0; m < 4; m++) {
                mma_tf32(d[m][n], ah[m], bh0, bh1);
                mma_tf32(d[m][n], ah[m], bl0, bl1);
                mma_tf32(d[m][n], al[m], bh0, bh1);
            }
        }
    }

    // ---- epilogue: add bias, store float2 pairs (32B-sector friendly) ----
    #pragma unroll
    for (int m = 0; m < 4; m++) {
        int row = mB + warpM * 64 + m * 16 + (lane >> 2);
        #pragma unroll
        for (int n = 0; n < 4; n++) {
            int cl = warpN * 32 + n * 8 + 2 * (lane & 3);
            float b0 = sm[KO_SB + cl], b1 = sm[KO_SB + cl + 1];
            float2 lo2 = make_float2(d[m][n][0] + b0, d[m][n][1] + b1);
            float2 hi2 = make_float2(d[m][n][2] + b0, d[m][n][3] + b1);
            *(float2*)(out + (size_t)row * COUT + jB + cl)       = lo2;
            *(float2*)(out + (size_t)(row + 8) * COUT + jB + cl) = hi2;
        }
    }
}

// ---------------- launch ----------------
extern "C" void kernel_launch(void* const* d_in, const int* in_sizes, int n_in,
                              void* d_out, int out_size)
{
    (void)in_sizes; (void)n_in; (void)out_size;
    const float* x   = (const float*)d_in[0];
    const float* Wc  = (const float*)d_in[1];
    const float* Bc  = (const float*)d_in[2];
    const float* Wd0 = (const float*)d_in[3];
    const float* Bd0 = (const float*)d_in[4];
    const float* Ws0 = (const float*)d_in[5];
    const float* Bs0 = (const float*)d_in[6];
    const float* Wo0 = (const float*)d_in[7];
    const float* Bo0 = (const float*)d_in[8];
    const float* Wd1 = (const float*)d_in[9];
    const float* Bd1 = (const float*)d_in[10];
    const float* Ws1 = (const float*)d_in[11];
    const float* Bs1 = (const float*)d_in[12];
    // d_in[13]=wo1, d_in[14]=bo1: dead branch (z after block 1 is never used)
    const float* Wk1 = (const float*)d_in[15];
    const float* Bk1 = (const float*)d_in[16];
    const float* W2  = (const float*)d_in[17];
    const float* B2  = (const float*)d_in[18];
    float* out = (float*)d_out;

    cudaFuncSetAttribute(k_front, cudaFuncAttributeMaxDynamicSharedMemorySize, SMEM1_BYTES);
    cudaFuncSetAttribute(k_out_tc, cudaFuncAttributeMaxDynamicSharedMemorySize, KO_SMEM_BYTES);

    dim3 g1(T_LEN / TILE, B_SZ);     // 16 x 32 = 512 blocks
    k_front<<<g1, NT, SMEM1_BYTES>>>(x, Wc, Bc, Wd0, Bd0, Ws0, Bs0, Wo0, Bo0,
                                     Wd1, Bd1, Ws1, Bs1, Wk1, Bk1);

    dim3 g2(COUT / 64, (B_SZ * T_LEN) / 256);  // 7 x 512 = 3584 blocks
    k_out_tc<<<g2, 256, KO_SMEM_BYTES>>>(W2, B2, out);
}